// round 10
// baseline (speedup 1.0000x reference)
#include <cuda_runtime.h>
#include <cuda_fp16.h>
#include <cstdint>

#define TLEN 2048
#define HEADS 8
#define HDIM 32
#define BSZ 4
#define NEMB 256
#define NBH (BSZ*HEADS)

// fp16 staging buffers
__device__ __half g_Xh [(size_t)8192*256];
__device__ __half g_WAh[(size_t)768*256];
__device__ __half g_WPh[(size_t)256*256];
__device__ __half g_PEh[(size_t)HEADS*TLEN*32];
__device__ __half g_Qh [(size_t)NBH*TLEN*32];
__device__ __half g_Kh [(size_t)NBH*TLEN*32];
__device__ __half g_Vth[(size_t)NBH*32*TLEN];
__device__ __half g_Oh [(size_t)8192*256];

// ---------------------------------------------------------------------------
__device__ __forceinline__ uint32_t ph2(float a, float b) {
    __half2 h = __floats2half2_rn(a, b);
    return *reinterpret_cast<uint32_t*>(&h);
}
__device__ __forceinline__ void mma_f16(float c[4],
                                        uint32_t a0, uint32_t a1, uint32_t a2, uint32_t a3,
                                        uint32_t b0, uint32_t b1) {
    asm volatile(
        "mma.sync.aligned.m16n8k16.row.col.f32.f16.f16.f32 "
        "{%0,%1,%2,%3}, {%4,%5,%6,%7}, {%8,%9}, {%0,%1,%2,%3};\n"
        : "+f"(c[0]), "+f"(c[1]), "+f"(c[2]), "+f"(c[3])
        : "r"(a0), "r"(a1), "r"(a2), "r"(a3), "r"(b0), "r"(b1));
}
__device__ __forceinline__ int gpos(int k) {
    int jw = (k >> 1) & 7;
    return (k & ~15) + (((((jw & 3) << 1) | (jw >> 2))) << 1) + (k & 1);
}
__device__ __forceinline__ int wpos(int j) {
    return (j & 8) + (((j & 3) << 1) | ((j >> 2) & 1));
}
__device__ __forceinline__ uint32_t smem_u32(const void* p) {
    uint32_t a;
    asm("{ .reg .u64 t; cvta.to.shared.u64 t, %1; cvt.u32.u64 %0, t; }" : "=r"(a) : "l"(p));
    return a;
}
__device__ __forceinline__ void cpa16(uint32_t dst, const void* src) {
    asm volatile("cp.async.cg.shared.global [%0], [%1], 16;" :: "r"(dst), "l"(src));
}
#define CPA_COMMIT() asm volatile("cp.async.commit_group;" ::: "memory")
#define CPA_WAIT0()  asm volatile("cp.async.wait_group 0;" ::: "memory")

// ---------------------------------------------------------------------------
// Kernel 0: vectorized convert/permute (16 halves per thread)
// chunks: x 131072 | pos 32768 | waT 12288 | wpT 4096  => 180224 total
// ---------------------------------------------------------------------------
__global__ void prep_kernel(const float* __restrict__ x, const float* __restrict__ wa,
                            const float* __restrict__ pos, const float* __restrict__ wp) {
    int idx = blockIdx.x * 256 + threadIdx.x;
    float v[16];
    __half* dst;
    if (idx < 131072) {                    // x [8192][256]
        int m = idx >> 4, c16 = (idx & 15) << 4;
        const float4* s = (const float4*)&x[(size_t)m * 256 + c16];
#pragma unroll
        for (int q = 0; q < 4; q++) {
            float4 f = s[q];
            v[q*4] = f.x; v[q*4+1] = f.y; v[q*4+2] = f.z; v[q*4+3] = f.w;
        }
        dst = &g_Xh[(size_t)m * 256 + c16];
    } else if (idx < 163840) {             // pos [16384][32]
        int i2 = idx - 131072;
        int r = i2 >> 1, c16 = (i2 & 1) << 4;
        const float4* s = (const float4*)&pos[(size_t)r * 32 + c16];
#pragma unroll
        for (int q = 0; q < 4; q++) {
            float4 f = s[q];
            v[q*4] = f.x; v[q*4+1] = f.y; v[q*4+2] = f.z; v[q*4+3] = f.w;
        }
        dst = &g_PEh[(size_t)r * 32 + c16];
    } else if (idx < 176128) {             // wa^T [768][256]
        int i2 = idx - 163840;
        int n = i2 >> 4, c16 = (i2 & 15) << 4;
#pragma unroll
        for (int q = 0; q < 16; q++) v[q] = wa[(size_t)(c16 + q) * 768 + n];
        dst = &g_WAh[(size_t)n * 256 + c16];
    } else if (idx < 180224) {             // wp^T [256][256]
        int i2 = idx - 176128;
        int n = i2 >> 4, c16 = (i2 & 15) << 4;
#pragma unroll
        for (int q = 0; q < 16; q++) v[q] = wp[(size_t)(c16 + q) * 256 + n];
        dst = &g_WPh[(size_t)n * 256 + c16];
    } else return;
    uint32_t w[8];
#pragma unroll
    for (int j = 0; j < 8; j++) w[wpos(j)] = ph2(v[2*j], v[2*j+1]);
    *(uint4*)dst       = *(uint4*)&w[0];
    *(uint4*)(dst + 8) = *(uint4*)&w[4];
}

// ---------------------------------------------------------------------------
// Kernel 1: qkv = x @ w_attn (unchanged)
// ---------------------------------------------------------------------------
__global__ void __launch_bounds__(256) qkv_kernel() {
    __shared__ __align__(16) uint32_t Ash[2][128*24];
    __shared__ __align__(16) uint32_t Bsh[2][64*24];
    int tid = threadIdx.x, lane = tid & 31, wid = tid >> 5;
    int g = lane >> 2, t4 = lane & 3;
    int m0 = blockIdx.y * 128, n0 = blockIdx.x * 64;
    uint32_t aB = smem_u32(Ash), bB = smem_u32(Bsh);

    float acc[8][4] = {};

    auto issue = [&](int buf, int kk) {
#pragma unroll
        for (int p = 0; p < 2; p++) {
            int e = tid + p * 256;
            int row = e >> 2, seg = e & 3;
            cpa16(aB + (buf*3072 + row*24 + seg*4) * 4,
                  (const char*)g_Xh + ((size_t)(m0 + row) * 256 + kk) * 2 + seg * 16);
        }
        {
            int row = tid >> 2, seg = tid & 3;
            cpa16(bB + (buf*1536 + row*24 + seg*4) * 4,
                  (const char*)g_WAh + ((size_t)(n0 + row) * 256 + kk) * 2 + seg * 16);
        }
    };

    issue(0, 0);
    CPA_COMMIT();
    for (int it = 0; it < 8; it++) {
        CPA_WAIT0();
        __syncthreads();
        if (it < 7) { issue((it + 1) & 1, (it + 1) * 32); CPA_COMMIT(); }
        const uint32_t* Ab = Ash[it & 1];
        const uint32_t* Bb = Bsh[it & 1];
#pragma unroll
        for (int ks = 0; ks < 2; ks++) {
            uint2 aa0 = *(const uint2*)&Ab[(wid*16 + g)     * 24 + ks*8 + 2*t4];
            uint2 aa1 = *(const uint2*)&Ab[(wid*16 + g + 8) * 24 + ks*8 + 2*t4];
#pragma unroll
            for (int nt = 0; nt < 8; nt++) {
                uint2 bb = *(const uint2*)&Bb[(nt*8 + g) * 24 + ks*8 + 2*t4];
                mma_f16(acc[nt], aa0.x, aa1.x, aa0.y, aa1.y, bb.x, bb.y);
            }
        }
        __syncthreads();
    }

    int m = m0 + wid*16 + g;
    int b = m >> 11, t = m & 2047, t2 = t + 8;
    int bh = b * HEADS;
#pragma unroll
    for (int nt = 0; nt < 8; nt++) {
        int col = n0 + nt*8 + 2*t4;
        int part = col >> 8, cc = col & 255;
        int h = cc >> 5, d = cc & 31;
        size_t bhh = (size_t)(bh + h);
        if (part == 1) {
            const float s = 0.17677669529663687f;
            *(uint32_t*)&g_Qh[(bhh*2048 + t )*32 + d] = ph2(acc[nt][0]*s, acc[nt][1]*s);
            *(uint32_t*)&g_Qh[(bhh*2048 + t2)*32 + d] = ph2(acc[nt][2]*s, acc[nt][3]*s);
        } else if (part == 0) {
            int wp16 = wpos(d >> 1);
            ((uint32_t*)g_Kh)[(bhh*2048 + t )*16 + wp16] = ph2(acc[nt][0], acc[nt][1]);
            ((uint32_t*)g_Kh)[(bhh*2048 + t2)*16 + wp16] = ph2(acc[nt][2], acc[nt][3]);
        } else {
            int tp  = (t  & ~15) + (((((t  >> 1) & 3) << 1) | ((t  >> 3) & 1)) << 1) + (t  & 1);
            int tp2 = (t2 & ~15) + (((((t2 >> 1) & 3) << 1) | ((t2 >> 3) & 1)) << 1) + (t2 & 1);
            g_Vth[(bhh*32 + d    )*2048 + tp ] = __float2half_rn(acc[nt][0]);
            g_Vth[(bhh*32 + d + 1)*2048 + tp ] = __float2half_rn(acc[nt][1]);
            g_Vth[(bhh*32 + d    )*2048 + tp2] = __float2half_rn(acc[nt][2]);
            g_Vth[(bhh*32 + d + 1)*2048 + tp2] = __float2half_rn(acc[nt][3]);
        }
    }
}

// ---------------------------------------------------------------------------
// Kernel 2: flash attention. 256-row pe ring (&255 math), unconditional band
// stores into padded Ssh, deferred l reduction, 3 CTAs/SM.
// ---------------------------------------------------------------------------
#define KSB(i) ((i)*1536)          /* 2 x 64x24  */
#define VTB(i) (3072+(i)*1280)     /* 2 x 32x40  */
#define PEW 5632                   /* 256x24 = 6144 words */
#define SSW 11776                  /* half [128][96] = 6144 words */
#define ATTN_BYTES 71680

__global__ void __launch_bounds__(256, 3) attn_kernel() {
    extern __shared__ uint32_t smu[];
    uint32_t smb = smem_u32(smu);
    __half* Ssh = (__half*)(smu + SSW);

    int tid = threadIdx.x, lane = tid & 31, wid = tid >> 5;
    int g = lane >> 2, t4 = lane & 3;
    int h = blockIdx.y, b = blockIdx.z;
    int t0 = (int)(gridDim.x - 1 - blockIdx.x) * 128;
    int bh = b * HEADS + h;

    const char* Kg = (const char*)g_Kh  + (size_t)bh * 2048 * 64;
    const char* Vg = (const char*)g_Vth + (size_t)bh * 32 * 2048 * 2;
    const char* Pg = (const char*)g_PEh + (size_t)h * 2048 * 64;

    int r0l = wid * 16 + g, r1l = r0l + 8;

    uint32_t qa[2][4];
    {
        const __half* q0 = g_Qh + ((size_t)bh * 2048 + t0 + r0l) * 32;
        const __half* q1 = q0 + 8 * 32;
#pragma unroll
        for (int ks = 0; ks < 2; ks++) {
            qa[ks][0] = *(const uint32_t*)(q0 + ks*16 + 2*t4);
            qa[ks][1] = *(const uint32_t*)(q1 + ks*16 + 2*t4);
            qa[ks][2] = *(const uint32_t*)(q0 + ks*16 + 2*t4 + 8);
            qa[ks][3] = *(const uint32_t*)(q1 + ks*16 + 2*t4 + 8);
        }
    }

    auto fillKV = [&](int idx) {
        int buf = idx & 1, s0 = idx * 64;
        int row = tid >> 2, seg = tid & 3;
        cpa16(smb + (KSB(buf) + row*24 + seg*4) * 4,
              Kg + (size_t)(s0 + row) * 64 + seg * 16);
        int d = tid >> 3, seg8 = tid & 7;
        cpa16(smb + (VTB(buf) + d*40 + seg8*4) * 4,
              Vg + ((size_t)d * 2048 + s0) * 2 + seg8 * 16);
    };
    // exactly one cp.async per thread: 64 rows x 4 segs
    auto fillPE64 = [&](int abs0) {
        int rr = tid >> 2, seg = tid & 3;
        int ab = abs0 + rr;
        int slot = ab & 255;
        int gr = ab > 2047 ? 2047 : ab;
        cpa16(smb + (PEW + slot*24 + seg*4) * 4, Pg + (size_t)gr * 64 + seg * 16);
    };

    float o[4][4] = {};
    float l0s = 0.0f, l1s = 0.0f;
    int gbase0 = 1920 - t0;
    int nK = t0 / 64 + 2;
    int utlo = 14 - 2 * wid;

    fillKV(0);
    fillPE64(gbase0);
    fillPE64(gbase0 + 64);
    fillPE64(gbase0 + 128);
    CPA_COMMIT();

    for (int kt = 0; kt < nK; kt++) {
        CPA_WAIT0();
        __syncthreads();
        if (kt + 1 < nK) {
            fillKV(kt + 1);
            fillPE64(gbase0 + 192 + 64 * kt);
            CPA_COMMIT();
        }

        int s0 = kt * 64;
        const uint32_t* Ks  = smu + KSB(kt & 1);
        const uint32_t* Vth = smu + VTB(kt & 1);
        const uint32_t* Peh = smu + PEW;

        bool active = (t0 + wid * 16 + 15) >= s0;
        if (!active) continue;

        // ---- band mma -> padded fp16 smem (unconditional stores) ----
        int bm = (gbase0 + 64 * kt) & 255;
#pragma unroll
        for (int q5 = 0; q5 < 10; q5++) {
            int ut = utlo + q5;
            int br = (bm + ut*8 + g) & 255;
            float c[4] = {0,0,0,0};
#pragma unroll
            for (int ks = 0; ks < 2; ks++) {
                uint2 bb = *(const uint2*)&Peh[br*24 + ks*8 + 2*t4];
                mma_f16(c, qa[ks][0], qa[ks][1], qa[ks][2], qa[ks][3], bb.x, bb.y);
            }
            int j0 = ut*8 + 2*t4 + r0l - 111;   // = band col + 16 pad
            Ssh[r0l*96 + j0]     = __float2half_rn(c[0]);
            Ssh[r0l*96 + j0 + 1] = __float2half_rn(c[1]);
            Ssh[r1l*96 + j0 + 8]     = __float2half_rn(c[2]);
            Ssh[r1l*96 + j0 + 9]     = __float2half_rn(c[3]);
        }
        __syncwarp();

        // ---- chunked QK -> softmax -> PV ----
        int lim0 = t0 + r0l - s0;
        int lim1 = lim0 + 8;
        bool full = (lim0 >= 63);
#pragma unroll
        for (int ch = 0; ch < 4; ch++) {
            int nt0 = 2*ch, nt1 = 2*ch + 1;
            float c0[4] = {0,0,0,0}, c1[4] = {0,0,0,0};
#pragma unroll
            for (int ks = 0; ks < 2; ks++) {
                uint2 b0 = *(const uint2*)&Ks[(nt0*8 + g)*24 + ks*8 + 2*t4];
                uint2 b1 = *(const uint2*)&Ks[(nt1*8 + g)*24 + ks*8 + 2*t4];
                mma_f16(c0, qa[ks][0], qa[ks][1], qa[ks][2], qa[ks][3], b0.x, b0.y);
                mma_f16(c1, qa[ks][0], qa[ks][1], qa[ks][2], qa[ks][3], b1.x, b1.y);
            }
            int j0c = nt0*8 + 2*t4, j1c = nt1*8 + 2*t4;
            float2 f00 = __half22float2(*(const __half2*)&Ssh[r0l*96 + 16 + j0c]);
            float2 f01 = __half22float2(*(const __half2*)&Ssh[r1l*96 + 16 + j0c]);
            float2 f10 = __half22float2(*(const __half2*)&Ssh[r0l*96 + 16 + j1c]);
            float2 f11 = __half22float2(*(const __half2*)&Ssh[r1l*96 + 16 + j1c]);
            float e00 = __expf(c0[0] + f00.x - 4.0f);
            float e01 = __expf(c0[1] + f00.y - 4.0f);
            float e02 = __expf(c0[2] + f01.x - 4.0f);
            float e03 = __expf(c0[3] + f01.y - 4.0f);
            float e10 = __expf(c1[0] + f10.x - 4.0f);
            float e11 = __expf(c1[1] + f10.y - 4.0f);
            float e12 = __expf(c1[2] + f11.x - 4.0f);
            float e13 = __expf(c1[3] + f11.y - 4.0f);
            if (!full) {
                e00 = (j0c     <= lim0) ? e00 : 0.0f;
                e01 = (j0c + 1 <= lim0) ? e01 : 0.0f;
                e02 = (j0c     <= lim1) ? e02 : 0.0f;
                e03 = (j0c + 1 <= lim1) ? e03 : 0.0f;
                e10 = (j1c     <= lim0) ? e10 : 0.0f;
                e11 = (j1c + 1 <= lim0) ? e11 : 0.0f;
                e12 = (j1c     <= lim1) ? e12 : 0.0f;
                e13 = (j1c + 1 <= lim1) ? e13 : 0.0f;
            }
            l0s += e00 + e01 + e10 + e11;
            l1s += e02 + e03 + e12 + e13;
            uint32_t a0 = ph2(e00, e01);
            uint32_t a1 = ph2(e02, e03);
            uint32_t a2 = ph2(e10, e11);
            uint32_t a3 = ph2(e12, e13);
#pragma unroll
            for (int nt = 0; nt < 4; nt++) {
                uint2 bb = *(const uint2*)&Vth[(nt*8 + g)*40 + ch*8 + 2*t4];
                mma_f16(o[nt], a0, a1, a2, a3, bb.x, bb.y);
            }
        }
    }

    // ---- deferred l reduction (once per CTA) ----
    l0s += __shfl_xor_sync(0xffffffffu, l0s, 1);
    l0s += __shfl_xor_sync(0xffffffffu, l0s, 2);
    l1s += __shfl_xor_sync(0xffffffffu, l1s, 1);
    l1s += __shfl_xor_sync(0xffffffffu, l1s, 2);

    // ---- epilogue: fp16 g_Oh (k-permuted rows for proj) ----
    float inv0 = 1.0f / l0s, inv1 = 1.0f / l1s;
    size_t row0 = ((size_t)b * 2048 + t0 + r0l) * 256;
    size_t row1 = ((size_t)b * 2048 + t0 + r1l) * 256;
#pragma unroll
    for (int nt = 0; nt < 4; nt++) {
        int k = h*32 + nt*8 + 2*t4;
        int gp = gpos(k);
        *(uint32_t*)&g_Oh[row0 + gp] = ph2(o[nt][0]*inv0, o[nt][1]*inv0);
        *(uint32_t*)&g_Oh[row1 + gp] = ph2(o[nt][2]*inv1, o[nt][3]*inv1);
    }
}

// ---------------------------------------------------------------------------
// Kernel 3: out = O @ w_proj + b_proj (unchanged)
// ---------------------------------------------------------------------------
__global__ void __launch_bounds__(256) proj_kernel(const float* __restrict__ bias,
                                                   float* __restrict__ out) {
    __shared__ __align__(16) uint32_t Ash[2][128*24];
    __shared__ __align__(16) uint32_t Bsh[2][64*24];
    int tid = threadIdx.x, lane = tid & 31, wid = tid >> 5;
    int g = lane >> 2, t4 = lane & 3;
    int m0 = blockIdx.y * 128, n0 = blockIdx.x * 64;
    uint32_t aB = smem_u32(Ash), bB = smem_u32(Bsh);

    float acc[8][4] = {};

    auto issue = [&](int buf, int kk) {
#pragma unroll
        for (int p = 0; p < 2; p++) {
            int e = tid + p * 256;
            int row = e >> 2, seg = e & 3;
            cpa16(aB + (buf*3072 + row*24 + seg*4) * 4,
                  (const char*)g_Oh + ((size_t)(m0 + row) * 256 + kk) * 2 + seg * 16);
        }
        {
            int row = tid >> 2, seg = tid & 3;
            cpa16(bB + (buf*1536 + row*24 + seg*4) * 4,
                  (const char*)g_WPh + ((size_t)(n0 + row) * 256 + kk) * 2 + seg * 16);
        }
    };

    issue(0, 0);
    CPA_COMMIT();
    for (int it = 0; it < 8; it++) {
        CPA_WAIT0();
        __syncthreads();
        if (it < 7) { issue((it + 1) & 1, (it + 1) * 32); CPA_COMMIT(); }
        const uint32_t* Ab = Ash[it & 1];
        const uint32_t* Bb = Bsh[it & 1];
#pragma unroll
        for (int ks = 0; ks < 2; ks++) {
            uint2 aa0 = *(const uint2*)&Ab[(wid*16 + g)     * 24 + ks*8 + 2*t4];
            uint2 aa1 = *(const uint2*)&Ab[(wid*16 + g + 8) * 24 + ks*8 + 2*t4];
#pragma unroll
            for (int nt = 0; nt < 8; nt++) {
                uint2 bb = *(const uint2*)&Bb[(nt*8 + g) * 24 + ks*8 + 2*t4];
                mma_f16(acc[nt], aa0.x, aa1.x, aa0.y, aa1.y, bb.x, bb.y);
            }
        }
        __syncthreads();
    }

    int m = m0 + wid*16 + g;
#pragma unroll
    for (int nt = 0; nt < 8; nt++) {
        int n = n0 + nt*8 + 2*t4;
        float b0 = bias[n], b1 = bias[n+1];
        *(float2*)&out[(size_t)m * 256 + n]       = make_float2(acc[nt][0] + b0, acc[nt][1] + b1);
        *(float2*)&out[(size_t)(m + 8) * 256 + n] = make_float2(acc[nt][2] + b0, acc[nt][3] + b1);
    }
}

// ---------------------------------------------------------------------------
extern "C" void kernel_launch(void* const* d_in, const int* in_sizes, int n_in,
                              void* d_out, int out_size) {
    const float* x      = (const float*)d_in[0];
    const float* w_attn = (const float*)d_in[1];
    const float* pos    = (const float*)d_in[2];
    const float* w_proj = (const float*)d_in[3];
    const float* b_proj = (const float*)d_in[4];
    float* out = (float*)d_out;

    prep_kernel<<<704, 256>>>(x, w_attn, pos, w_proj);
    qkv_kernel<<<dim3(12, 64), 256>>>();

    static int attr_set = 0;
    if (!attr_set) {
        cudaFuncSetAttribute(attn_kernel, cudaFuncAttributeMaxDynamicSharedMemorySize,
                             ATTN_BYTES);
        attr_set = 1;
    }
    attn_kernel<<<dim3(16, 8, 4), 256, ATTN_BYTES>>>();

    proj_kernel<<<dim3(4, 64), 256>>>(b_proj, out);
}

// round 11
// speedup vs baseline: 1.2212x; 1.2212x over previous
#include <cuda_runtime.h>
#include <cuda_fp16.h>
#include <cstdint>

#define TLEN 2048
#define HEADS 8
#define HDIM 32
#define BSZ 4
#define NEMB 256
#define NBH (BSZ*HEADS)

// fp16 staging buffers
__device__ __half g_Xh [(size_t)8192*256];
__device__ __half g_WAh[(size_t)768*256];
__device__ __half g_WPh[(size_t)256*256];
__device__ __half g_PEh[(size_t)HEADS*TLEN*32];
__device__ __half g_Qh [(size_t)NBH*TLEN*32];
__device__ __half g_Kh [(size_t)NBH*TLEN*32];
__device__ __half g_Vth[(size_t)NBH*32*TLEN];
__device__ __half g_Oh [(size_t)8192*256];

// ---------------------------------------------------------------------------
__device__ __forceinline__ uint32_t ph2(float a, float b) {
    __half2 h = __floats2half2_rn(a, b);
    return *reinterpret_cast<uint32_t*>(&h);
}
__device__ __forceinline__ void mma_f16(float c[4],
                                        uint32_t a0, uint32_t a1, uint32_t a2, uint32_t a3,
                                        uint32_t b0, uint32_t b1) {
    asm volatile(
        "mma.sync.aligned.m16n8k16.row.col.f32.f16.f16.f32 "
        "{%0,%1,%2,%3}, {%4,%5,%6,%7}, {%8,%9}, {%0,%1,%2,%3};\n"
        : "+f"(c[0]), "+f"(c[1]), "+f"(c[2]), "+f"(c[3])
        : "r"(a0), "r"(a1), "r"(a2), "r"(a3), "r"(b0), "r"(b1));
}
__device__ __forceinline__ int gpos(int k) {
    int jw = (k >> 1) & 7;
    return (k & ~15) + (((((jw & 3) << 1) | (jw >> 2))) << 1) + (k & 1);
}
__device__ __forceinline__ int wpos(int j) {
    return (j & 8) + (((j & 3) << 1) | ((j >> 2) & 1));
}
__device__ __forceinline__ uint32_t smem_u32(const void* p) {
    uint32_t a;
    asm("{ .reg .u64 t; cvta.to.shared.u64 t, %1; cvt.u32.u64 %0, t; }" : "=r"(a) : "l"(p));
    return a;
}
__device__ __forceinline__ void cpa16(uint32_t dst, const void* src) {
    asm volatile("cp.async.cg.shared.global [%0], [%1], 16;" :: "r"(dst), "l"(src));
}
#define CPA_COMMIT() asm volatile("cp.async.commit_group;" ::: "memory")
#define CPA_WAIT0()  asm volatile("cp.async.wait_group 0;" ::: "memory")

// ---------------------------------------------------------------------------
// Kernel 0: vectorized convert/permute (16 halves per thread)
// chunks: x 131072 | pos 32768 | waT 12288 | wpT 4096  => 180224 total
// ---------------------------------------------------------------------------
__global__ void prep_kernel(const float* __restrict__ x, const float* __restrict__ wa,
                            const float* __restrict__ pos, const float* __restrict__ wp) {
    int idx = blockIdx.x * 256 + threadIdx.x;
    float v[16];
    __half* dst;
    if (idx < 131072) {                    // x [8192][256]
        int m = idx >> 4, c16 = (idx & 15) << 4;
        const float4* s = (const float4*)&x[(size_t)m * 256 + c16];
#pragma unroll
        for (int q = 0; q < 4; q++) {
            float4 f = s[q];
            v[q*4] = f.x; v[q*4+1] = f.y; v[q*4+2] = f.z; v[q*4+3] = f.w;
        }
        dst = &g_Xh[(size_t)m * 256 + c16];
    } else if (idx < 163840) {             // pos [16384][32]
        int i2 = idx - 131072;
        int r = i2 >> 1, c16 = (i2 & 1) << 4;
        const float4* s = (const float4*)&pos[(size_t)r * 32 + c16];
#pragma unroll
        for (int q = 0; q < 4; q++) {
            float4 f = s[q];
            v[q*4] = f.x; v[q*4+1] = f.y; v[q*4+2] = f.z; v[q*4+3] = f.w;
        }
        dst = &g_PEh[(size_t)r * 32 + c16];
    } else if (idx < 176128) {             // wa^T [768][256]
        int i2 = idx - 163840;
        int n = i2 >> 4, c16 = (i2 & 15) << 4;
#pragma unroll
        for (int q = 0; q < 16; q++) v[q] = wa[(size_t)(c16 + q) * 768 + n];
        dst = &g_WAh[(size_t)n * 256 + c16];
    } else if (idx < 180224) {             // wp^T [256][256]
        int i2 = idx - 176128;
        int n = i2 >> 4, c16 = (i2 & 15) << 4;
#pragma unroll
        for (int q = 0; q < 16; q++) v[q] = wp[(size_t)(c16 + q) * 256 + n];
        dst = &g_WPh[(size_t)n * 256 + c16];
    } else return;
    uint32_t w[8];
#pragma unroll
    for (int j = 0; j < 8; j++) w[wpos(j)] = ph2(v[2*j], v[2*j+1]);
    *(uint4*)dst       = *(uint4*)&w[0];
    *(uint4*)(dst + 8) = *(uint4*)&w[4];
}

// ---------------------------------------------------------------------------
// Kernel 1: qkv = x @ w_attn (round-9 version, unchanged)
// ---------------------------------------------------------------------------
__global__ void __launch_bounds__(256) qkv_kernel() {
    __shared__ __align__(16) uint32_t Ash[2][128*24];
    __shared__ __align__(16) uint32_t Bsh[2][64*24];
    int tid = threadIdx.x, lane = tid & 31, wid = tid >> 5;
    int g = lane >> 2, t4 = lane & 3;
    int m0 = blockIdx.y * 128, n0 = blockIdx.x * 64;
    uint32_t aB = smem_u32(Ash), bB = smem_u32(Bsh);

    float acc[8][4] = {};

    auto issue = [&](int buf, int kk) {
#pragma unroll
        for (int p = 0; p < 2; p++) {
            int e = tid + p * 256;
            int row = e >> 2, seg = e & 3;
            cpa16(aB + (buf*3072 + row*24 + seg*4) * 4,
                  (const char*)g_Xh + ((size_t)(m0 + row) * 256 + kk) * 2 + seg * 16);
        }
        {
            int row = tid >> 2, seg = tid & 3;
            cpa16(bB + (buf*1536 + row*24 + seg*4) * 4,
                  (const char*)g_WAh + ((size_t)(n0 + row) * 256 + kk) * 2 + seg * 16);
        }
    };

    issue(0, 0);
    CPA_COMMIT();
    for (int it = 0; it < 8; it++) {
        CPA_WAIT0();
        __syncthreads();
        if (it < 7) { issue((it + 1) & 1, (it + 1) * 32); CPA_COMMIT(); }
        const uint32_t* Ab = Ash[it & 1];
        const uint32_t* Bb = Bsh[it & 1];
#pragma unroll
        for (int ks = 0; ks < 2; ks++) {
            uint2 aa0 = *(const uint2*)&Ab[(wid*16 + g)     * 24 + ks*8 + 2*t4];
            uint2 aa1 = *(const uint2*)&Ab[(wid*16 + g + 8) * 24 + ks*8 + 2*t4];
#pragma unroll
            for (int nt = 0; nt < 8; nt++) {
                uint2 bb = *(const uint2*)&Bb[(nt*8 + g) * 24 + ks*8 + 2*t4];
                mma_f16(acc[nt], aa0.x, aa1.x, aa0.y, aa1.y, bb.x, bb.y);
            }
        }
        __syncthreads();
    }

    int m = m0 + wid*16 + g;
    int b = m >> 11, t = m & 2047, t2 = t + 8;
    int bh = b * HEADS;
#pragma unroll
    for (int nt = 0; nt < 8; nt++) {
        int col = n0 + nt*8 + 2*t4;
        int part = col >> 8, cc = col & 255;
        int h = cc >> 5, d = cc & 31;
        size_t bhh = (size_t)(bh + h);
        if (part == 1) {
            const float s = 0.17677669529663687f;
            *(uint32_t*)&g_Qh[(bhh*2048 + t )*32 + d] = ph2(acc[nt][0]*s, acc[nt][1]*s);
            *(uint32_t*)&g_Qh[(bhh*2048 + t2)*32 + d] = ph2(acc[nt][2]*s, acc[nt][3]*s);
        } else if (part == 0) {
            int wp16 = wpos(d >> 1);
            ((uint32_t*)g_Kh)[(bhh*2048 + t )*16 + wp16] = ph2(acc[nt][0], acc[nt][1]);
            ((uint32_t*)g_Kh)[(bhh*2048 + t2)*16 + wp16] = ph2(acc[nt][2], acc[nt][3]);
        } else {
            int tp  = (t  & ~15) + (((((t  >> 1) & 3) << 1) | ((t  >> 3) & 1)) << 1) + (t  & 1);
            int tp2 = (t2 & ~15) + (((((t2 >> 1) & 3) << 1) | ((t2 >> 3) & 1)) << 1) + (t2 & 1);
            g_Vth[(bhh*32 + d    )*2048 + tp ] = __float2half_rn(acc[nt][0]);
            g_Vth[(bhh*32 + d + 1)*2048 + tp ] = __float2half_rn(acc[nt][1]);
            g_Vth[(bhh*32 + d    )*2048 + tp2] = __float2half_rn(acc[nt][2]);
            g_Vth[(bhh*32 + d + 1)*2048 + tp2] = __float2half_rn(acc[nt][3]);
        }
    }
}

// ---------------------------------------------------------------------------
// Kernel 2: flash attention (round-9 version: 320-row pe ring, stride-80 Ssh,
// predicated band stores, per-iter l reduction, 3 CTAs/SM)
// ---------------------------------------------------------------------------
#define KSB(i) ((i)*1536)          /* 2 x 64x24  */
#define VTB(i) (3072+(i)*1280)     /* 2 x 32x40  */
#define PEW 5632                   /* 320x24 = 7680 words */
#define SSW 13312                  /* half [128][80] = 5120 words */
#define ATTN_BYTES 73728

__global__ void __launch_bounds__(256, 3) attn_kernel() {
    extern __shared__ uint32_t smu[];
    uint32_t smb = smem_u32(smu);
    __half* Ssh = (__half*)(smu + SSW);

    int tid = threadIdx.x, lane = tid & 31, wid = tid >> 5;
    int g = lane >> 2, t4 = lane & 3;
    int h = blockIdx.y, b = blockIdx.z;
    int t0 = (int)(gridDim.x - 1 - blockIdx.x) * 128;
    int bh = b * HEADS + h;

    const char* Kg = (const char*)g_Kh  + (size_t)bh * 2048 * 64;
    const char* Vg = (const char*)g_Vth + (size_t)bh * 32 * 2048 * 2;
    const char* Pg = (const char*)g_PEh + (size_t)h * 2048 * 64;

    int r0l = wid * 16 + g, r1l = r0l + 8;

    uint32_t qa[2][4];
    {
        const __half* q0 = g_Qh + ((size_t)bh * 2048 + t0 + r0l) * 32;
        const __half* q1 = q0 + 8 * 32;
#pragma unroll
        for (int ks = 0; ks < 2; ks++) {
            qa[ks][0] = *(const uint32_t*)(q0 + ks*16 + 2*t4);
            qa[ks][1] = *(const uint32_t*)(q1 + ks*16 + 2*t4);
            qa[ks][2] = *(const uint32_t*)(q0 + ks*16 + 2*t4 + 8);
            qa[ks][3] = *(const uint32_t*)(q1 + ks*16 + 2*t4 + 8);
        }
    }

    auto fillKV = [&](int idx) {
        int buf = idx & 1, s0 = idx * 64;
        int row = tid >> 2, seg = tid & 3;
        cpa16(smb + (KSB(buf) + row*24 + seg*4) * 4,
              Kg + (size_t)(s0 + row) * 64 + seg * 16);
        int d = tid >> 3, seg8 = tid & 7;
        cpa16(smb + (VTB(buf) + d*40 + seg8*4) * 4,
              Vg + ((size_t)d * 2048 + s0) * 2 + seg8 * 16);
    };
    auto fillPE = [&](int abs0, int n4) {
        for (int e = tid; e < n4; e += 256) {
            int rr = e >> 2, seg = e & 3;
            int ab = abs0 + rr;
            int slot = ab % 320;
            int gr = ab > 2047 ? 2047 : ab;
            cpa16(smb + (PEW + slot*24 + seg*4) * 4, Pg + (size_t)gr * 64 + seg * 16);
        }
    };

    float o[4][4] = {};
    float l0s = 0.0f, l1s = 0.0f;
    int gbase0 = 1920 - t0;
    int nK = t0 / 64 + 2;
    int utlo = 14 - 2 * wid;

    fillKV(0);
    fillPE(gbase0, 768);          // 192 rows: full first window
    CPA_COMMIT();

    for (int kt = 0; kt < nK; kt++) {
        CPA_WAIT0();
        __syncthreads();
        if (kt + 1 < nK) {
            fillKV(kt + 1);
            fillPE(gbase0 + 192 + 64 * kt, 256);   // 64 new rows for kt+1
            CPA_COMMIT();
        }

        int s0 = kt * 64;
        int gbase = gbase0 + 64 * kt;
        const uint32_t* Ks  = smu + KSB(kt & 1);
        const uint32_t* Vth = smu + VTB(kt & 1);
        const uint32_t* Peh = smu + PEW;

        bool active = (t0 + wid * 16 + 15) >= s0;
        if (!active) continue;

        // ---- band mma -> fp16 smem (diagonal-shift exchange) ----
        int bm = gbase % 320;
#pragma unroll
        for (int q5 = 0; q5 < 10; q5++) {
            int ut = utlo + q5;
            int br = bm + ut*8 + g; if (br >= 320) br -= 320;
            float c[4] = {0,0,0,0};
#pragma unroll
            for (int ks = 0; ks < 2; ks++) {
                uint2 bb = *(const uint2*)&Peh[br*24 + ks*8 + 2*t4];
                mma_f16(c, qa[ks][0], qa[ks][1], qa[ks][2], qa[ks][3], bb.x, bb.y);
            }
            int j0 = ut*8 + 2*t4 + r0l - 127;
            if ((unsigned)j0     < 64u) Ssh[r0l*80 + j0]     = __float2half_rn(c[0]);
            if ((unsigned)(j0+1) < 64u) Ssh[r0l*80 + j0 + 1] = __float2half_rn(c[1]);
            int j1 = j0 + 8;
            if ((unsigned)j1     < 64u) Ssh[r1l*80 + j1]     = __float2half_rn(c[2]);
            if ((unsigned)(j1+1) < 64u) Ssh[r1l*80 + j1 + 1] = __float2half_rn(c[3]);
        }
        __syncwarp();

        // ---- chunked QK -> softmax -> PV (4 chunks of 16 cols) ----
        int lim0 = t0 + r0l - s0;
        int lim1 = lim0 + 8;
        bool full = (lim0 >= 63);
        float s0sum = 0.0f, s1sum = 0.0f;
#pragma unroll
        for (int ch = 0; ch < 4; ch++) {
            int nt0 = 2*ch, nt1 = 2*ch + 1;
            float c0[4] = {0,0,0,0}, c1[4] = {0,0,0,0};
#pragma unroll
            for (int ks = 0; ks < 2; ks++) {
                uint2 b0 = *(const uint2*)&Ks[(nt0*8 + g)*24 + ks*8 + 2*t4];
                uint2 b1 = *(const uint2*)&Ks[(nt1*8 + g)*24 + ks*8 + 2*t4];
                mma_f16(c0, qa[ks][0], qa[ks][1], qa[ks][2], qa[ks][3], b0.x, b0.y);
                mma_f16(c1, qa[ks][0], qa[ks][1], qa[ks][2], qa[ks][3], b1.x, b1.y);
            }
            int j0c = nt0*8 + 2*t4, j1c = nt1*8 + 2*t4;
            float2 f00 = __half22float2(*(const __half2*)&Ssh[r0l*80 + j0c]);
            float2 f01 = __half22float2(*(const __half2*)&Ssh[r1l*80 + j0c]);
            float2 f10 = __half22float2(*(const __half2*)&Ssh[r0l*80 + j1c]);
            float2 f11 = __half22float2(*(const __half2*)&Ssh[r1l*80 + j1c]);
            float e00 = __expf(c0[0] + f00.x - 4.0f);
            float e01 = __expf(c0[1] + f00.y - 4.0f);
            float e02 = __expf(c0[2] + f01.x - 4.0f);
            float e03 = __expf(c0[3] + f01.y - 4.0f);
            float e10 = __expf(c1[0] + f10.x - 4.0f);
            float e11 = __expf(c1[1] + f10.y - 4.0f);
            float e12 = __expf(c1[2] + f11.x - 4.0f);
            float e13 = __expf(c1[3] + f11.y - 4.0f);
            if (!full) {
                e00 = (j0c     <= lim0) ? e00 : 0.0f;
                e01 = (j0c + 1 <= lim0) ? e01 : 0.0f;
                e02 = (j0c     <= lim1) ? e02 : 0.0f;
                e03 = (j0c + 1 <= lim1) ? e03 : 0.0f;
                e10 = (j1c     <= lim0) ? e10 : 0.0f;
                e11 = (j1c + 1 <= lim0) ? e11 : 0.0f;
                e12 = (j1c     <= lim1) ? e12 : 0.0f;
                e13 = (j1c + 1 <= lim1) ? e13 : 0.0f;
            }
            s0sum += e00 + e01 + e10 + e11;
            s1sum += e02 + e03 + e12 + e13;
            uint32_t a0 = ph2(e00, e01);
            uint32_t a1 = ph2(e02, e03);
            uint32_t a2 = ph2(e10, e11);
            uint32_t a3 = ph2(e12, e13);
#pragma unroll
            for (int nt = 0; nt < 4; nt++) {
                uint2 bb = *(const uint2*)&Vth[(nt*8 + g)*40 + ch*8 + 2*t4];
                mma_f16(o[nt], a0, a1, a2, a3, bb.x, bb.y);
            }
        }
        s0sum += __shfl_xor_sync(0xffffffffu, s0sum, 1);
        s0sum += __shfl_xor_sync(0xffffffffu, s0sum, 2);
        s1sum += __shfl_xor_sync(0xffffffffu, s1sum, 1);
        s1sum += __shfl_xor_sync(0xffffffffu, s1sum, 2);
        l0s += s0sum; l1s += s1sum;
    }

    // ---- epilogue: fp16 g_Oh (k-permuted rows for proj) ----
    float inv0 = 1.0f / l0s, inv1 = 1.0f / l1s;
    size_t row0 = ((size_t)b * 2048 + t0 + r0l) * 256;
    size_t row1 = ((size_t)b * 2048 + t0 + r1l) * 256;
#pragma unroll
    for (int nt = 0; nt < 4; nt++) {
        int k = h*32 + nt*8 + 2*t4;
        int gp = gpos(k);
        *(uint32_t*)&g_Oh[row0 + gp] = ph2(o[nt][0]*inv0, o[nt][1]*inv0);
        *(uint32_t*)&g_Oh[row1 + gp] = ph2(o[nt][2]*inv1, o[nt][3]*inv1);
    }
}

// ---------------------------------------------------------------------------
// Kernel 3: out = O @ w_proj + b_proj (unchanged)
// ---------------------------------------------------------------------------
__global__ void __launch_bounds__(256) proj_kernel(const float* __restrict__ bias,
                                                   float* __restrict__ out) {
    __shared__ __align__(16) uint32_t Ash[2][128*24];
    __shared__ __align__(16) uint32_t Bsh[2][64*24];
    int tid = threadIdx.x, lane = tid & 31, wid = tid >> 5;
    int g = lane >> 2, t4 = lane & 3;
    int m0 = blockIdx.y * 128, n0 = blockIdx.x * 64;
    uint32_t aB = smem_u32(Ash), bB = smem_u32(Bsh);

    float acc[8][4] = {};

    auto issue = [&](int buf, int kk) {
#pragma unroll
        for (int p = 0; p < 2; p++) {
            int e = tid + p * 256;
            int row = e >> 2, seg = e & 3;
            cpa16(aB + (buf*3072 + row*24 + seg*4) * 4,
                  (const char*)g_Oh + ((size_t)(m0 + row) * 256 + kk) * 2 + seg * 16);
        }
        {
            int row = tid >> 2, seg = tid & 3;
            cpa16(bB + (buf*1536 + row*24 + seg*4) * 4,
                  (const char*)g_WPh + ((size_t)(n0 + row) * 256 + kk) * 2 + seg * 16);
        }
    };

    issue(0, 0);
    CPA_COMMIT();
    for (int it = 0; it < 8; it++) {
        CPA_WAIT0();
        __syncthreads();
        if (it < 7) { issue((it + 1) & 1, (it + 1) * 32); CPA_COMMIT(); }
        const uint32_t* Ab = Ash[it & 1];
        const uint32_t* Bb = Bsh[it & 1];
#pragma unroll
        for (int ks = 0; ks < 2; ks++) {
            uint2 aa0 = *(const uint2*)&Ab[(wid*16 + g)     * 24 + ks*8 + 2*t4];
            uint2 aa1 = *(const uint2*)&Ab[(wid*16 + g + 8) * 24 + ks*8 + 2*t4];
#pragma unroll
            for (int nt = 0; nt < 8; nt++) {
                uint2 bb = *(const uint2*)&Bb[(nt*8 + g) * 24 + ks*8 + 2*t4];
                mma_f16(acc[nt], aa0.x, aa1.x, aa0.y, aa1.y, bb.x, bb.y);
            }
        }
        __syncthreads();
    }

    int m = m0 + wid*16 + g;
#pragma unroll
    for (int nt = 0; nt < 8; nt++) {
        int n = n0 + nt*8 + 2*t4;
        float b0 = bias[n], b1 = bias[n+1];
        *(float2*)&out[(size_t)m * 256 + n]       = make_float2(acc[nt][0] + b0, acc[nt][1] + b1);
        *(float2*)&out[(size_t)(m + 8) * 256 + n] = make_float2(acc[nt][2] + b0, acc[nt][3] + b1);
    }
}

// ---------------------------------------------------------------------------
extern "C" void kernel_launch(void* const* d_in, const int* in_sizes, int n_in,
                              void* d_out, int out_size) {
    const float* x      = (const float*)d_in[0];
    const float* w_attn = (const float*)d_in[1];
    const float* pos    = (const float*)d_in[2];
    const float* w_proj = (const float*)d_in[3];
    const float* b_proj = (const float*)d_in[4];
    float* out = (float*)d_out;

    prep_kernel<<<704, 256>>>(x, w_attn, pos, w_proj);
    qkv_kernel<<<dim3(12, 64), 256>>>();

    static int attr_set = 0;
    if (!attr_set) {
        cudaFuncSetAttribute(attn_kernel, cudaFuncAttributeMaxDynamicSharedMemorySize,
                             ATTN_BYTES);
        attr_set = 1;
    }
    attn_kernel<<<dim3(16, 8, 4), 256, ATTN_BYTES>>>();

    proj_kernel<<<dim3(4, 64), 256>>>(b_proj, out);
}

// round 12
// speedup vs baseline: 1.2576x; 1.0298x over previous
#include <cuda_runtime.h>
#include <cuda_fp16.h>
#include <cstdint>

#define TLEN 2048
#define HEADS 8
#define HDIM 32
#define BSZ 4
#define NEMB 256
#define NBH (BSZ*HEADS)

// fp16 staging buffers
__device__ __half g_Xh [(size_t)8192*256];
__device__ __half g_WAh[(size_t)768*256];
__device__ __half g_WPh[(size_t)256*256];
__device__ __half g_PEh[(size_t)HEADS*TLEN*32];
__device__ __half g_Qh [(size_t)NBH*TLEN*32];
__device__ __half g_Kh [(size_t)NBH*TLEN*32];
__device__ __half g_Vth[(size_t)NBH*32*TLEN];
__device__ __half g_Oh [(size_t)8192*256];
// split-K partials
__device__ float  g_Of [(size_t)2*8192*256];
__device__ float  g_Lf [(size_t)2*NBH*TLEN];

// ---------------------------------------------------------------------------
__device__ __forceinline__ uint32_t ph2(float a, float b) {
    __half2 h = __floats2half2_rn(a, b);
    return *reinterpret_cast<uint32_t*>(&h);
}
__device__ __forceinline__ void mma_f16(float c[4],
                                        uint32_t a0, uint32_t a1, uint32_t a2, uint32_t a3,
                                        uint32_t b0, uint32_t b1) {
    asm volatile(
        "mma.sync.aligned.m16n8k16.row.col.f32.f16.f16.f32 "
        "{%0,%1,%2,%3}, {%4,%5,%6,%7}, {%8,%9}, {%0,%1,%2,%3};\n"
        : "+f"(c[0]), "+f"(c[1]), "+f"(c[2]), "+f"(c[3])
        : "r"(a0), "r"(a1), "r"(a2), "r"(a3), "r"(b0), "r"(b1));
}
__device__ __forceinline__ int gpos(int k) {
    int jw = (k >> 1) & 7;
    return (k & ~15) + (((((jw & 3) << 1) | (jw >> 2))) << 1) + (k & 1);
}
__device__ __forceinline__ int wpos(int j) {
    return (j & 8) + (((j & 3) << 1) | ((j >> 2) & 1));
}
__device__ __forceinline__ uint32_t smem_u32(const void* p) {
    uint32_t a;
    asm("{ .reg .u64 t; cvta.to.shared.u64 t, %1; cvt.u32.u64 %0, t; }" : "=r"(a) : "l"(p));
    return a;
}
__device__ __forceinline__ void cpa16(uint32_t dst, const void* src) {
    asm volatile("cp.async.cg.shared.global [%0], [%1], 16;" :: "r"(dst), "l"(src));
}
#define CPA_COMMIT() asm volatile("cp.async.commit_group;" ::: "memory")
#define CPA_WAIT0()  asm volatile("cp.async.wait_group 0;" ::: "memory")

// ---------------------------------------------------------------------------
// Kernel 0: vectorized convert/permute (16 halves per thread)
// ---------------------------------------------------------------------------
__global__ void prep_kernel(const float* __restrict__ x, const float* __restrict__ wa,
                            const float* __restrict__ pos, const float* __restrict__ wp) {
    int idx = blockIdx.x * 256 + threadIdx.x;
    float v[16];
    __half* dst;
    if (idx < 131072) {                    // x [8192][256]
        int m = idx >> 4, c16 = (idx & 15) << 4;
        const float4* s = (const float4*)&x[(size_t)m * 256 + c16];
#pragma unroll
        for (int q = 0; q < 4; q++) {
            float4 f = s[q];
            v[q*4] = f.x; v[q*4+1] = f.y; v[q*4+2] = f.z; v[q*4+3] = f.w;
        }
        dst = &g_Xh[(size_t)m * 256 + c16];
    } else if (idx < 163840) {             // pos [16384][32]
        int i2 = idx - 131072;
        int r = i2 >> 1, c16 = (i2 & 1) << 4;
        const float4* s = (const float4*)&pos[(size_t)r * 32 + c16];
#pragma unroll
        for (int q = 0; q < 4; q++) {
            float4 f = s[q];
            v[q*4] = f.x; v[q*4+1] = f.y; v[q*4+2] = f.z; v[q*4+3] = f.w;
        }
        dst = &g_PEh[(size_t)r * 32 + c16];
    } else if (idx < 176128) {             // wa^T [768][256]
        int i2 = idx - 163840;
        int n = i2 >> 4, c16 = (i2 & 15) << 4;
#pragma unroll
        for (int q = 0; q < 16; q++) v[q] = wa[(size_t)(c16 + q) * 768 + n];
        dst = &g_WAh[(size_t)n * 256 + c16];
    } else if (idx < 180224) {             // wp^T [256][256]
        int i2 = idx - 176128;
        int n = i2 >> 4, c16 = (i2 & 15) << 4;
#pragma unroll
        for (int q = 0; q < 16; q++) v[q] = wp[(size_t)(c16 + q) * 256 + n];
        dst = &g_WPh[(size_t)n * 256 + c16];
    } else return;
    uint32_t w[8];
#pragma unroll
    for (int j = 0; j < 8; j++) w[wpos(j)] = ph2(v[2*j], v[2*j+1]);
    *(uint4*)dst       = *(uint4*)&w[0];
    *(uint4*)(dst + 8) = *(uint4*)&w[4];
}

// ---------------------------------------------------------------------------
// Kernel 1: qkv = x @ w_attn (unchanged)
// ---------------------------------------------------------------------------
__global__ void __launch_bounds__(256) qkv_kernel() {
    __shared__ __align__(16) uint32_t Ash[2][128*24];
    __shared__ __align__(16) uint32_t Bsh[2][64*24];
    int tid = threadIdx.x, lane = tid & 31, wid = tid >> 5;
    int g = lane >> 2, t4 = lane & 3;
    int m0 = blockIdx.y * 128, n0 = blockIdx.x * 64;
    uint32_t aB = smem_u32(Ash), bB = smem_u32(Bsh);

    float acc[8][4] = {};

    auto issue = [&](int buf, int kk) {
#pragma unroll
        for (int p = 0; p < 2; p++) {
            int e = tid + p * 256;
            int row = e >> 2, seg = e & 3;
            cpa16(aB + (buf*3072 + row*24 + seg*4) * 4,
                  (const char*)g_Xh + ((size_t)(m0 + row) * 256 + kk) * 2 + seg * 16);
        }
        {
            int row = tid >> 2, seg = tid & 3;
            cpa16(bB + (buf*1536 + row*24 + seg*4) * 4,
                  (const char*)g_WAh + ((size_t)(n0 + row) * 256 + kk) * 2 + seg * 16);
        }
    };

    issue(0, 0);
    CPA_COMMIT();
    for (int it = 0; it < 8; it++) {
        CPA_WAIT0();
        __syncthreads();
        if (it < 7) { issue((it + 1) & 1, (it + 1) * 32); CPA_COMMIT(); }
        const uint32_t* Ab = Ash[it & 1];
        const uint32_t* Bb = Bsh[it & 1];
#pragma unroll
        for (int ks = 0; ks < 2; ks++) {
            uint2 aa0 = *(const uint2*)&Ab[(wid*16 + g)     * 24 + ks*8 + 2*t4];
            uint2 aa1 = *(const uint2*)&Ab[(wid*16 + g + 8) * 24 + ks*8 + 2*t4];
#pragma unroll
            for (int nt = 0; nt < 8; nt++) {
                uint2 bb = *(const uint2*)&Bb[(nt*8 + g) * 24 + ks*8 + 2*t4];
                mma_f16(acc[nt], aa0.x, aa1.x, aa0.y, aa1.y, bb.x, bb.y);
            }
        }
        __syncthreads();
    }

    int m = m0 + wid*16 + g;
    int b = m >> 11, t = m & 2047, t2 = t + 8;
    int bh = b * HEADS;
#pragma unroll
    for (int nt = 0; nt < 8; nt++) {
        int col = n0 + nt*8 + 2*t4;
        int part = col >> 8, cc = col & 255;
        int h = cc >> 5, d = cc & 31;
        size_t bhh = (size_t)(bh + h);
        if (part == 1) {
            const float s = 0.17677669529663687f;
            *(uint32_t*)&g_Qh[(bhh*2048 + t )*32 + d] = ph2(acc[nt][0]*s, acc[nt][1]*s);
            *(uint32_t*)&g_Qh[(bhh*2048 + t2)*32 + d] = ph2(acc[nt][2]*s, acc[nt][3]*s);
        } else if (part == 0) {
            int wp16 = wpos(d >> 1);
            ((uint32_t*)g_Kh)[(bhh*2048 + t )*16 + wp16] = ph2(acc[nt][0], acc[nt][1]);
            ((uint32_t*)g_Kh)[(bhh*2048 + t2)*16 + wp16] = ph2(acc[nt][2], acc[nt][3]);
        } else {
            int tp  = (t  & ~15) + (((((t  >> 1) & 3) << 1) | ((t  >> 3) & 1)) << 1) + (t  & 1);
            int tp2 = (t2 & ~15) + (((((t2 >> 1) & 3) << 1) | ((t2 >> 3) & 1)) << 1) + (t2 & 1);
            g_Vth[(bhh*32 + d    )*2048 + tp ] = __float2half_rn(acc[nt][0]);
            g_Vth[(bhh*32 + d + 1)*2048 + tp ] = __float2half_rn(acc[nt][1]);
            g_Vth[(bhh*32 + d    )*2048 + tp2] = __float2half_rn(acc[nt][2]);
            g_Vth[(bhh*32 + d + 1)*2048 + tp2] = __float2half_rn(acc[nt][3]);
        }
    }
}

// ---------------------------------------------------------------------------
// Kernel 2: split-K flash attention. blockIdx.z = b*2 + split; each split
// processes half the key tiles, writes unnormalized fp32 partial O + l.
// Inner loop identical to the measured-good round-9/11 version.
// ---------------------------------------------------------------------------
#define KSB(i) ((i)*1536)          /* 2 x 64x24  */
#define VTB(i) (3072+(i)*1280)     /* 2 x 32x40  */
#define PEW 5632                   /* 320x24 = 7680 words */
#define SSW 13312                  /* half [128][80] = 5120 words */
#define ATTN_BYTES 73728

__global__ void __launch_bounds__(256, 3) attn_kernel() {
    extern __shared__ uint32_t smu[];
    uint32_t smb = smem_u32(smu);
    __half* Ssh = (__half*)(smu + SSW);

    int tid = threadIdx.x, lane = tid & 31, wid = tid >> 5;
    int g = lane >> 2, t4 = lane & 3;
    int h = blockIdx.y;
    int b = blockIdx.z >> 1, split = blockIdx.z & 1;
    int t0 = (int)(gridDim.x - 1 - blockIdx.x) * 128;
    int bh = b * HEADS + h;

    const char* Kg = (const char*)g_Kh  + (size_t)bh * 2048 * 64;
    const char* Vg = (const char*)g_Vth + (size_t)bh * 32 * 2048 * 2;
    const char* Pg = (const char*)g_PEh + (size_t)h * 2048 * 64;

    int r0l = wid * 16 + g, r1l = r0l + 8;

    uint32_t qa[2][4];
    {
        const __half* q0 = g_Qh + ((size_t)bh * 2048 + t0 + r0l) * 32;
        const __half* q1 = q0 + 8 * 32;
#pragma unroll
        for (int ks = 0; ks < 2; ks++) {
            qa[ks][0] = *(const uint32_t*)(q0 + ks*16 + 2*t4);
            qa[ks][1] = *(const uint32_t*)(q1 + ks*16 + 2*t4);
            qa[ks][2] = *(const uint32_t*)(q0 + ks*16 + 2*t4 + 8);
            qa[ks][3] = *(const uint32_t*)(q1 + ks*16 + 2*t4 + 8);
        }
    }

    auto fillKV = [&](int idx) {
        int buf = idx & 1, s0 = idx * 64;
        int row = tid >> 2, seg = tid & 3;
        cpa16(smb + (KSB(buf) + row*24 + seg*4) * 4,
              Kg + (size_t)(s0 + row) * 64 + seg * 16);
        int d = tid >> 3, seg8 = tid & 7;
        cpa16(smb + (VTB(buf) + d*40 + seg8*4) * 4,
              Vg + ((size_t)d * 2048 + s0) * 2 + seg8 * 16);
    };
    auto fillPE = [&](int abs0, int n4) {
        for (int e = tid; e < n4; e += 256) {
            int rr = e >> 2, seg = e & 3;
            int ab = abs0 + rr;
            int slot = ab % 320;
            int gr = ab > 2047 ? 2047 : ab;
            cpa16(smb + (PEW + slot*24 + seg*4) * 4, Pg + (size_t)gr * 64 + seg * 16);
        }
    };

    float o[4][4] = {};
    float l0s = 0.0f, l1s = 0.0f;
    int gbase0 = 1920 - t0;
    int nKt = t0 / 64 + 2;
    int nK0 = (nKt + 1) >> 1;
    int ktBeg = split ? nK0 : 0;
    int ktEnd = split ? nKt : nK0;
    int utlo = 14 - 2 * wid;

    fillKV(ktBeg);
    fillPE(gbase0 + 64 * ktBeg, 768);    // 192 rows: window for first tile
    CPA_COMMIT();

    for (int kt = ktBeg; kt < ktEnd; kt++) {
        CPA_WAIT0();
        __syncthreads();
        if (kt + 1 < ktEnd) {
            fillKV(kt + 1);
            fillPE(gbase0 + 192 + 64 * kt, 256);   // 64 new rows for kt+1
            CPA_COMMIT();
        }

        int s0 = kt * 64;
        int gbase = gbase0 + 64 * kt;
        const uint32_t* Ks  = smu + KSB(kt & 1);
        const uint32_t* Vth = smu + VTB(kt & 1);
        const uint32_t* Peh = smu + PEW;

        bool active = (t0 + wid * 16 + 15) >= s0;
        if (!active) continue;

        // ---- band mma -> fp16 smem (diagonal-shift exchange) ----
        int bm = gbase % 320;
#pragma unroll
        for (int q5 = 0; q5 < 10; q5++) {
            int ut = utlo + q5;
            int br = bm + ut*8 + g; if (br >= 320) br -= 320;
            float c[4] = {0,0,0,0};
#pragma unroll
            for (int ks = 0; ks < 2; ks++) {
                uint2 bb = *(const uint2*)&Peh[br*24 + ks*8 + 2*t4];
                mma_f16(c, qa[ks][0], qa[ks][1], qa[ks][2], qa[ks][3], bb.x, bb.y);
            }
            int j0 = ut*8 + 2*t4 + r0l - 127;
            if ((unsigned)j0     < 64u) Ssh[r0l*80 + j0]     = __float2half_rn(c[0]);
            if ((unsigned)(j0+1) < 64u) Ssh[r0l*80 + j0 + 1] = __float2half_rn(c[1]);
            int j1 = j0 + 8;
            if ((unsigned)j1     < 64u) Ssh[r1l*80 + j1]     = __float2half_rn(c[2]);
            if ((unsigned)(j1+1) < 64u) Ssh[r1l*80 + j1 + 1] = __float2half_rn(c[3]);
        }
        __syncwarp();

        // ---- chunked QK -> softmax -> PV (4 chunks of 16 cols) ----
        int lim0 = t0 + r0l - s0;
        int lim1 = lim0 + 8;
        bool full = (lim0 >= 63);
        float s0sum = 0.0f, s1sum = 0.0f;
#pragma unroll
        for (int ch = 0; ch < 4; ch++) {
            int nt0 = 2*ch, nt1 = 2*ch + 1;
            float c0[4] = {0,0,0,0}, c1[4] = {0,0,0,0};
#pragma unroll
            for (int ks = 0; ks < 2; ks++) {
                uint2 b0 = *(const uint2*)&Ks[(nt0*8 + g)*24 + ks*8 + 2*t4];
                uint2 b1 = *(const uint2*)&Ks[(nt1*8 + g)*24 + ks*8 + 2*t4];
                mma_f16(c0, qa[ks][0], qa[ks][1], qa[ks][2], qa[ks][3], b0.x, b0.y);
                mma_f16(c1, qa[ks][0], qa[ks][1], qa[ks][2], qa[ks][3], b1.x, b1.y);
            }
            int j0c = nt0*8 + 2*t4, j1c = nt1*8 + 2*t4;
            float2 f00 = __half22float2(*(const __half2*)&Ssh[r0l*80 + j0c]);
            float2 f01 = __half22float2(*(const __half2*)&Ssh[r1l*80 + j0c]);
            float2 f10 = __half22float2(*(const __half2*)&Ssh[r0l*80 + j1c]);
            float2 f11 = __half22float2(*(const __half2*)&Ssh[r1l*80 + j1c]);
            float e00 = __expf(c0[0] + f00.x - 4.0f);
            float e01 = __expf(c0[1] + f00.y - 4.0f);
            float e02 = __expf(c0[2] + f01.x - 4.0f);
            float e03 = __expf(c0[3] + f01.y - 4.0f);
            float e10 = __expf(c1[0] + f10.x - 4.0f);
            float e11 = __expf(c1[1] + f10.y - 4.0f);
            float e12 = __expf(c1[2] + f11.x - 4.0f);
            float e13 = __expf(c1[3] + f11.y - 4.0f);
            if (!full) {
                e00 = (j0c     <= lim0) ? e00 : 0.0f;
                e01 = (j0c + 1 <= lim0) ? e01 : 0.0f;
                e02 = (j0c     <= lim1) ? e02 : 0.0f;
                e03 = (j0c + 1 <= lim1) ? e03 : 0.0f;
                e10 = (j1c     <= lim0) ? e10 : 0.0f;
                e11 = (j1c + 1 <= lim0) ? e11 : 0.0f;
                e12 = (j1c     <= lim1) ? e12 : 0.0f;
                e13 = (j1c + 1 <= lim1) ? e13 : 0.0f;
            }
            s0sum += e00 + e01 + e10 + e11;
            s1sum += e02 + e03 + e12 + e13;
            uint32_t a0 = ph2(e00, e01);
            uint32_t a1 = ph2(e02, e03);
            uint32_t a2 = ph2(e10, e11);
            uint32_t a3 = ph2(e12, e13);
#pragma unroll
            for (int nt = 0; nt < 4; nt++) {
                uint2 bb = *(const uint2*)&Vth[(nt*8 + g)*40 + ch*8 + 2*t4];
                mma_f16(o[nt], a0, a1, a2, a3, bb.x, bb.y);
            }
        }
        s0sum += __shfl_xor_sync(0xffffffffu, s0sum, 1);
        s0sum += __shfl_xor_sync(0xffffffffu, s0sum, 2);
        s1sum += __shfl_xor_sync(0xffffffffu, s1sum, 1);
        s1sum += __shfl_xor_sync(0xffffffffu, s1sum, 2);
        l0s += s0sum; l1s += s1sum;
    }

    // ---- epilogue: unnormalized fp32 partials + l ----
    float* Op = g_Of + (size_t)split * 8192 * 256;
    size_t row0 = ((size_t)b * 2048 + t0 + r0l) * 256;
    size_t row1 = ((size_t)b * 2048 + t0 + r1l) * 256;
#pragma unroll
    for (int nt = 0; nt < 4; nt++) {
        int gp = gpos(h*32 + nt*8 + 2*t4);
        *(float2*)&Op[row0 + gp] = make_float2(o[nt][0], o[nt][1]);
        *(float2*)&Op[row1 + gp] = make_float2(o[nt][2], o[nt][3]);
    }
    if (t4 == 0) {
        float* Lp = g_Lf + (size_t)split * NBH * 2048 + (size_t)bh * 2048;
        Lp[t0 + r0l] = l0s;
        Lp[t0 + r1l] = l1s;
    }
}

// ---------------------------------------------------------------------------
// Kernel 2b: combine splits -> fp16 g_Oh
// ---------------------------------------------------------------------------
__global__ void combine_kernel() {
    int idx = blockIdx.x * 256 + threadIdx.x;      // 262144 total
    int m = idx >> 5, k0 = (idx & 31) * 8;
    int t = m & 2047, b = m >> 11, h = k0 >> 5;
    size_t lix = (size_t)(b * HEADS + h) * 2048 + t;
    float l = g_Lf[lix] + g_Lf[(size_t)NBH * 2048 + lix];
    float inv = 1.0f / l;
    size_t base = (size_t)m * 256 + k0;
    float4 a0 = *(const float4*)&g_Of[base];
    float4 a1 = *(const float4*)&g_Of[base + 4];
    float4 b0 = *(const float4*)&g_Of[(size_t)8192*256 + base];
    float4 b1 = *(const float4*)&g_Of[(size_t)8192*256 + base + 4];
    uint32_t w[4];
    w[0] = ph2((a0.x + b0.x) * inv, (a0.y + b0.y) * inv);
    w[1] = ph2((a0.z + b0.z) * inv, (a0.w + b0.w) * inv);
    w[2] = ph2((a1.x + b1.x) * inv, (a1.y + b1.y) * inv);
    w[3] = ph2((a1.z + b1.z) * inv, (a1.w + b1.w) * inv);
    *(uint4*)&g_Oh[base] = *(uint4*)w;
}

// ---------------------------------------------------------------------------
// Kernel 3: out = O @ w_proj + b_proj (unchanged)
// ---------------------------------------------------------------------------
__global__ void __launch_bounds__(256) proj_kernel(const float* __restrict__ bias,
                                                   float* __restrict__ out) {
    __shared__ __align__(16) uint32_t Ash[2][128*24];
    __shared__ __align__(16) uint32_t Bsh[2][64*24];
    int tid = threadIdx.x, lane = tid & 31, wid = tid >> 5;
    int g = lane >> 2, t4 = lane & 3;
    int m0 = blockIdx.y * 128, n0 = blockIdx.x * 64;
    uint32_t aB = smem_u32(Ash), bB = smem_u32(Bsh);

    float acc[8][4] = {};

    auto issue = [&](int buf, int kk) {
#pragma unroll
        for (int p = 0; p < 2; p++) {
            int e = tid + p * 256;
            int row = e >> 2, seg = e & 3;
            cpa16(aB + (buf*3072 + row*24 + seg*4) * 4,
                  (const char*)g_Oh + ((size_t)(m0 + row) * 256 + kk) * 2 + seg * 16);
        }
        {
            int row = tid >> 2, seg = tid & 3;
            cpa16(bB + (buf*1536 + row*24 + seg*4) * 4,
                  (const char*)g_WPh + ((size_t)(n0 + row) * 256 + kk) * 2 + seg * 16);
        }
    };

    issue(0, 0);
    CPA_COMMIT();
    for (int it = 0; it < 8; it++) {
        CPA_WAIT0();
        __syncthreads();
        if (it < 7) { issue((it + 1) & 1, (it + 1) * 32); CPA_COMMIT(); }
        const uint32_t* Ab = Ash[it & 1];
        const uint32_t* Bb = Bsh[it & 1];
#pragma unroll
        for (int ks = 0; ks < 2; ks++) {
            uint2 aa0 = *(const uint2*)&Ab[(wid*16 + g)     * 24 + ks*8 + 2*t4];
            uint2 aa1 = *(const uint2*)&Ab[(wid*16 + g + 8) * 24 + ks*8 + 2*t4];
#pragma unroll
            for (int nt = 0; nt < 8; nt++) {
                uint2 bb = *(const uint2*)&Bb[(nt*8 + g) * 24 + ks*8 + 2*t4];
                mma_f16(acc[nt], aa0.x, aa1.x, aa0.y, aa1.y, bb.x, bb.y);
            }
        }
        __syncthreads();
    }

    int m = m0 + wid*16 + g;
#pragma unroll
    for (int nt = 0; nt < 8; nt++) {
        int n = n0 + nt*8 + 2*t4;
        float b0 = bias[n], b1 = bias[n+1];
        *(float2*)&out[(size_t)m * 256 + n]       = make_float2(acc[nt][0] + b0, acc[nt][1] + b1);
        *(float2*)&out[(size_t)(m + 8) * 256 + n] = make_float2(acc[nt][2] + b0, acc[nt][3] + b1);
    }
}

// ---------------------------------------------------------------------------
extern "C" void kernel_launch(void* const* d_in, const int* in_sizes, int n_in,
                              void* d_out, int out_size) {
    const float* x      = (const float*)d_in[0];
    const float* w_attn = (const float*)d_in[1];
    const float* pos    = (const float*)d_in[2];
    const float* w_proj = (const float*)d_in[3];
    const float* b_proj = (const float*)d_in[4];
    float* out = (float*)d_out;

    prep_kernel<<<704, 256>>>(x, w_attn, pos, w_proj);
    qkv_kernel<<<dim3(12, 64), 256>>>();

    static int attr_set = 0;
    if (!attr_set) {
        cudaFuncSetAttribute(attn_kernel, cudaFuncAttributeMaxDynamicSharedMemorySize,
                             ATTN_BYTES);
        attr_set = 1;
    }
    attn_kernel<<<dim3(16, 8, 8), 256, ATTN_BYTES>>>();
    combine_kernel<<<1024, 256>>>();

    proj_kernel<<<dim3(4, 64), 256>>>(b_proj, out);
}